// round 6
// baseline (speedup 1.0000x reference)
#include <cuda_runtime.h>
#include <math.h>

#define BB   4
#define SS   512
#define HH   256
#define VV   32000
#define MM   (BB*SS)     // 2048

// ---------------- device scratch (no allocation anywhere) ----------------
__device__ float g_embT[HH * MM];              // [k][bt]                2 MB
__device__ float g_xp[(size_t)MM * 768];       // [bt][row]              6 MB
__device__ float g_hsR[(size_t)MM * HH];       // [bt][perm(k)] rounded  2 MB
__device__ float g_WoutR[(size_t)VV * HH];     // [n][perm(k)] rounded  33 MB

// RNA round fp32 -> tf32 bit pattern (round-to-nearest, ties away)
__device__ __forceinline__ float rna_tf32(float v) {
    unsigned b = __float_as_uint(v);
    b = (b + 0x1000u) & 0xFFFFE000u;
    return __uint_as_float(b);
}
// permute k within 16-chunks: value at orig k goes to pos (k&~15) | ((k&3)<<2) | ((k>>2)&3)
__device__ __forceinline__ int permk(int k) {
    return (k & ~15) | ((k & 3) << 2) | ((k >> 2) & 3);
}

// ---------------- kernel A: gather emb -> transposed ----------------------
__global__ void gather_kernel(const int* __restrict__ x,
                              const float* __restrict__ emb)
{
    const int bt  = blockIdx.x;
    const int tid = threadIdx.x;             // 0..63
    const int tok = x[bt];
    const float4 v = *(const float4*)(emb + (size_t)tok * HH + tid * 4);
    const int k = tid * 4;
    g_embT[(k + 0) * MM + bt] = v.x;
    g_embT[(k + 1) * MM + bt] = v.y;
    g_embT[(k + 2) * MM + bt] = v.z;
    g_embT[(k + 3) * MM + bt] = v.w;
}

// ---------------- kernel B: xp = emb @ W_ih^T + b_ih ----------------------
__global__ void __launch_bounds__(256) inproj_kernel(
    const float* __restrict__ W_ih, const float* __restrict__ b_ih)
{
    __shared__ float sW[16 * 256];
    const int r0 = blockIdx.y * 16;
    const int bt = blockIdx.x * 256 + threadIdx.x;
    for (int i = threadIdx.x; i < 16 * 256; i += 256)
        sW[i] = W_ih[(size_t)r0 * 256 + i];
    __syncthreads();

    float acc[16];
#pragma unroll
    for (int ri = 0; ri < 16; ri++) acc[ri] = 0.f;

#pragma unroll 4
    for (int k = 0; k < HH; k++) {
        const float e = g_embT[k * MM + bt];
#pragma unroll
        for (int ri = 0; ri < 16; ri++)
            acc[ri] += e * sW[ri * 256 + k];
    }
    float* o = g_xp + (size_t)bt * 768 + r0;
#pragma unroll
    for (int ri = 0; ri < 16; ri++)
        o[ri] = acc[ri] + b_ih[r0 + ri];
}

// ---------------- kernel B2: round + permute W_out -------------------------
__global__ void __launch_bounds__(256) roundw_kernel(const float* __restrict__ Wout)
{
    const int n = blockIdx.x;
    const int k = threadIdx.x;
    g_WoutR[(size_t)n * HH + permk(k)] = rna_tf32(Wout[(size_t)n * HH + k]);
}

// ---------------- kernel C: GRU recurrence (mbarrier sync) -----------------
// 4 clusters (1 per batch) x 8 CTAs x 384 threads.
// CTA rank owns hidden columns [rank*32, rank*32+32).
// h_t stored into all 8 CTAs' sh[t&1] via st.shared::cluster; completion
// tracked by count-8 mbarriers (one release-arrive per source CTA).
__device__ __forceinline__ void mbar_wait_acq(unsigned mb, unsigned parity)
{
    asm volatile(
        "{\n\t"
        ".reg .pred P;\n\t"
        "WL%=:\n\t"
        "mbarrier.try_wait.parity.acquire.cluster.shared::cta.b64 P, [%0], %1;\n\t"
        "@!P bra WL%=;\n\t"
        "}"
        :: "r"(mb), "r"(parity) : "memory");
}

__global__ void __launch_bounds__(384, 1) __cluster_dims__(8, 1, 1)
gru_kernel(const float* __restrict__ W_hh, const float* __restrict__ b_hh)
{
    __shared__ float  sh[2][HH];     // double-buffered h
    __shared__ float4 spart[96];     // partial dots [g*32 + col].kc
    __shared__ alignas(8) unsigned long long mbars[2];

    const int tid  = threadIdx.x;
    const int w    = tid >> 5;       // 0..11
    const int lane = tid & 31;
    const int g    = w >> 2;         // gate 0..2
    const int kc   = w & 3;          // k-chunk 0..3
    unsigned rank;
    asm("mov.u32 %0, %%cluster_ctarank;" : "=r"(rank));
    const int batch = blockIdx.x >> 3;
    const int col   = (int)rank * 32 + lane;

    // persistent W_hh slice in registers, packed as f32x2 pairs
    unsigned long long wreg[32];
    {
        const ulonglong2* wp =
            (const ulonglong2*)(W_hh + (size_t)(g * HH + col) * HH + kc * 64);
#pragma unroll
        for (int i = 0; i < 16; i++) {
            const ulonglong2 wv = wp[i];
            wreg[2 * i + 0] = wv.x;
            wreg[2 * i + 1] = wv.y;
        }
    }

    float bhr = 0.f, bhz = 0.f, bhn = 0.f;
    int gcol = 0;
    if (tid < 32) {
        gcol = (int)rank * 32 + tid;
        bhr = b_hh[0 * HH + gcol];
        bhz = b_hh[1 * HH + gcol];
        bhn = b_hh[2 * HH + gcol];
    }

    const unsigned sh_addr = (unsigned)__cvta_generic_to_shared(&sh[0][0]);
    const unsigned mb_addr = (unsigned)__cvta_generic_to_shared(&mbars[0]);

    // init: h0 = 0, count-8 mbarriers (auto-re-arm every phase)
    if (tid < HH) sh[0][tid] = 0.f;
    if (tid == 0) {
        asm volatile("mbarrier.init.shared.b64 [%0], 8;" :: "r"(mb_addr)     : "memory");
        asm volatile("mbarrier.init.shared.b64 [%0], 8;" :: "r"(mb_addr + 8) : "memory");
    }
    __syncthreads();
    // all CTAs' mbarriers initialized before any remote arrive can land
    asm volatile("barrier.cluster.arrive.aligned;" ::: "memory");
    asm volatile("barrier.cluster.wait.aligned;"   ::: "memory");

    unsigned par0 = 0, par1 = 0;

    for (int t = 1; t <= SS; t++) {
        const int cur = (t - 1) & 1;
        const int nxt = t & 1;

        // xp loads issued BEFORE the wait (latency hidden)
        float xr = 0.f, xz = 0.f, xn = 0.f;
        if (tid < 32) {
            const size_t base = (size_t)(batch * SS + t - 1) * 768 + gcol;
            xr = g_xp[base + 0 * HH];
            xz = g_xp[base + 1 * HH];
            xn = g_xp[base + 2 * HH];
        }

        if (t > 1) {
            const unsigned mb = mb_addr + (unsigned)cur * 8u;
            mbar_wait_acq(mb, cur ? par1 : par0);
            if (cur) par1 ^= 1u; else par0 ^= 1u;
        }

        // partial dot: packed f32x2, two accumulators
        {
            const float* hb = &sh[cur][kc * 64];
            unsigned long long a0 = 0ULL, a1 = 0ULL;
#pragma unroll
            for (int i = 0; i < 64; i += 8) {
                const ulonglong2 h0 = *(const ulonglong2*)(hb + i);
                const ulonglong2 h1 = *(const ulonglong2*)(hb + i + 4);
                asm("fma.rn.f32x2 %0, %1, %2, %0;"
                    : "+l"(a0) : "l"(wreg[i / 2 + 0]), "l"(h0.x));
                asm("fma.rn.f32x2 %0, %1, %2, %0;"
                    : "+l"(a1) : "l"(wreg[i / 2 + 1]), "l"(h0.y));
                asm("fma.rn.f32x2 %0, %1, %2, %0;"
                    : "+l"(a0) : "l"(wreg[i / 2 + 2]), "l"(h1.x));
                asm("fma.rn.f32x2 %0, %1, %2, %0;"
                    : "+l"(a1) : "l"(wreg[i / 2 + 3]), "l"(h1.y));
            }
            const float s = __uint_as_float((unsigned)(a0 & 0xffffffffu))
                          + __uint_as_float((unsigned)(a0 >> 32))
                          + __uint_as_float((unsigned)(a1 & 0xffffffffu))
                          + __uint_as_float((unsigned)(a1 >> 32));
            ((float*)&spart[g * 32 + lane])[kc] = s;
        }
        __syncthreads();   // also: all reads of sh[cur] complete before stores/arrives

        if (tid < 32) {    // gate warp (warp 0, all 32 lanes)
            const float4 p0 = spart[0 * 32 + tid];
            const float4 p1 = spart[1 * 32 + tid];
            const float4 p2 = spart[2 * 32 + tid];
            const float hr = p0.x + p0.y + p0.z + p0.w + bhr;
            const float hz = p1.x + p1.y + p1.z + p1.w + bhz;
            const float hn = p2.x + p2.y + p2.z + p2.w + bhn;
            const float r  = 1.f / (1.f + __expf(-(xr + hr)));
            const float z  = 1.f / (1.f + __expf(-(xz + hz)));
            const float nv = xn + r * hn;
            const float n  = 1.f - 2.f / (__expf(2.f * nv) + 1.f);   // tanh
            const float ho = sh[cur][gcol];
            const float hnew = (1.f - z) * n + z * ho;

            // store h_new into all 8 cluster CTAs' sh[nxt][gcol]
            const unsigned dst = sh_addr + (unsigned)(nxt * HH + gcol) * 4u;
#pragma unroll
            for (int rk = 0; rk < 8; rk++) {
                unsigned rem;
                asm volatile("mapa.shared::cluster.u32 %0, %1, %2;"
                             : "=r"(rem) : "r"(dst), "r"((unsigned)rk));
                asm volatile("st.shared::cluster.f32 [%0], %1;"
                             :: "r"(rem), "f"(hnew) : "memory");
            }
            // GEMM copy: rounded to TF32 (RNA) + k-permuted
            g_hsR[(size_t)(batch * SS + t - 1) * HH + permk(gcol)] = rna_tf32(hnew);

            __syncwarp(0xffffffffu);
            if (tid < 8) {   // one release-arrive per destination CTA
                asm volatile("fence.acq_rel.cluster;" ::: "memory");
                const unsigned mbd = mb_addr + (unsigned)nxt * 8u;
                unsigned remm;
                asm volatile("mapa.shared::cluster.u32 %0, %1, %2;"
                             : "=r"(remm) : "r"(mbd), "r"((unsigned)tid));
                asm volatile("mbarrier.arrive.release.cluster.shared::cluster.b64 _, [%0];"
                             :: "r"(remm) : "memory");
            }
        }
    }
    // drain: final (t=512) deliveries land on mbar[0]; wait so no CTA exits
    // while peer stores into our smem are in flight
    mbar_wait_acq(mb_addr, par0);
}

// ---------------- kernel D: output GEMM (TF32 mma, permuted 128-bit LDS) ---
__device__ __forceinline__ void cp16(unsigned smem_dst, const void* gsrc) {
    asm volatile("cp.async.cg.shared.global [%0], [%1], 16;"
                 :: "r"(smem_dst), "l"(gsrc) : "memory");
}
__device__ __forceinline__ void mma_tf32(float* d, unsigned a0, unsigned a1,
                                         unsigned a2, unsigned a3,
                                         unsigned b0, unsigned b1) {
    asm volatile(
        "mma.sync.aligned.m16n8k8.row.col.f32.tf32.tf32.f32 "
        "{%0,%1,%2,%3}, {%4,%5,%6,%7}, {%8,%9}, {%0,%1,%2,%3};"
        : "+f"(d[0]), "+f"(d[1]), "+f"(d[2]), "+f"(d[3])
        : "r"(a0), "r"(a1), "r"(a2), "r"(a3), "r"(b0), "r"(b1));
}

__global__ void __launch_bounds__(256, 2) gemm_out_kernel(
    const float* __restrict__ bout, const int* __restrict__ x,
    float* __restrict__ out)
{
    __shared__ unsigned sA[2][128 * 16];   // 8 KB per stage
    __shared__ unsigned sB[2][128 * 16];

    const int m0   = blockIdx.y * 128;
    const int n0   = blockIdx.x * 128;
    const int tid  = threadIdx.x;
    const int lane = tid & 31;
    const int wid  = tid >> 5;          // 0..7
    const int wm   = wid & 3;           // 4 warps along m
    const int wn   = wid >> 2;          // 2 warps along n
    const int gid  = lane >> 2;
    const int tig  = lane & 3;

    float acc[2][8][4];
#pragma unroll
    for (int mi = 0; mi < 2; mi++)
#pragma unroll
        for (int ni = 0; ni < 8; ni++)
#pragma unroll
            for (int q = 0; q < 4; q++) acc[mi][ni][q] = 0.f;

    // loader: 512 16B segments per matrix per chunk; 2 per thread each
    const int seg0 = tid * 2;
    const unsigned sA0 = (unsigned)__cvta_generic_to_shared(&sA[0][0]);
    const unsigned sB0 = (unsigned)__cvta_generic_to_shared(&sB[0][0]);

    // prefetch chunk 0 into stage 0
#pragma unroll
    for (int q = 0; q < 2; q++) {
        const int idx = seg0 + q;
        const int row = idx >> 2, quad = idx & 3;
        cp16(sA0 + (unsigned)(row * 16 + quad * 4) * 4u,
             g_hsR + (size_t)(m0 + row) * HH + quad * 4);
        cp16(sB0 + (unsigned)(row * 16 + quad * 4) * 4u,
             g_WoutR + (size_t)(n0 + row) * HH + quad * 4);
    }
    asm volatile("cp.async.commit_group;" ::: "memory");

    for (int c = 0; c < 16; c++) {
        const int s = c & 1;
        if (c + 1 < 16) {
            const unsigned so = (unsigned)((c + 1) & 1) * (128 * 16 * 4);
            const int k0 = (c + 1) * 16;
#pragma unroll
            for (int q = 0; q < 2; q++) {
                const int idx = seg0 + q;
                const int row = idx >> 2, quad = idx & 3;
                cp16(sA0 + so + (unsigned)(row * 16 + quad * 4) * 4u,
                     g_hsR + (size_t)(m0 + row) * HH + k0 + quad * 4);
                cp16(sB0 + so + (unsigned)(row * 16 + quad * 4) * 4u,
                     g_WoutR + (size_t)(n0 + row) * HH + k0 + quad * 4);
            }
            asm volatile("cp.async.commit_group;" ::: "memory");
            asm volatile("cp.async.wait_group 1;" ::: "memory");
        } else {
            asm volatile("cp.async.wait_group 0;" ::: "memory");
        }
        __syncthreads();

        // A fragments: 4x LDS.128 (conflict-free: banks 16g+4t disjoint/phase)
        uint4 av[2][2];
#pragma unroll
        for (int mi = 0; mi < 2; mi++) {
            const int base = wm * 32 + mi * 16;
            av[mi][0] = *(const uint4*)&sA[s][(base + gid) * 16 + tig * 4];
            av[mi][1] = *(const uint4*)&sA[s][(base + gid + 8) * 16 + tig * 4];
        }
        // B in pairs of ni to bound registers; mma dependency distance 4
#pragma unroll
        for (int nip = 0; nip < 4; nip++) {
            uint4 bv[2];
#pragma unroll
            for (int nj = 0; nj < 2; nj++) {
                const int nb = wn * 64 + (nip * 2 + nj) * 8;
                bv[nj] = *(const uint4*)&sB[s][(nb + gid) * 16 + tig * 4];
            }
            const unsigned* b0p = (const unsigned*)&bv[0];
            const unsigned* b1p = (const unsigned*)&bv[1];
#pragma unroll
            for (int ks = 0; ks < 2; ks++) {
#pragma unroll
                for (int mi = 0; mi < 2; mi++) {
                    const unsigned* r0 = (const unsigned*)&av[mi][0];
                    const unsigned* r1 = (const unsigned*)&av[mi][1];
                    mma_tf32(acc[mi][nip * 2 + 0],
                             r0[2 * ks], r1[2 * ks], r0[2 * ks + 1], r1[2 * ks + 1],
                             b0p[2 * ks], b0p[2 * ks + 1]);
                    mma_tf32(acc[mi][nip * 2 + 1],
                             r0[2 * ks], r1[2 * ks], r0[2 * ks + 1], r1[2 * ks + 1],
                             b1p[2 * ks], b1p[2 * ks + 1]);
                }
            }
        }
        __syncthreads();
    }

    // epilogue: bias + symbolic mask + store
#pragma unroll
    for (int mi = 0; mi < 2; mi++) {
        const int rbase = m0 + wm * 32 + mi * 16;
#pragma unroll
        for (int half = 0; half < 2; half++) {
            const int row = rbase + gid + half * 8;    // bt
            const int t   = row & (SS - 1);
            const bool pz = (t > 0) && (x[row - 1] == 0);
#pragma unroll
            for (int ni = 0; ni < 8; ni++) {
                const int col = n0 + wn * 64 + ni * 8 + tig * 2;
                float v0 = acc[mi][ni][half * 2 + 0] + bout[col];
                float v1 = acc[mi][ni][half * 2 + 1] + bout[col + 1];
                if (pz) {
                    if (col >= 3)     v0 = -INFINITY;
                    if (col + 1 >= 3) v1 = -INFINITY;
                }
                *(float2*)(out + (size_t)row * VV + col) = make_float2(v0, v1);
            }
        }
    }
}

// ---------------- launch ---------------------------------------------------
extern "C" void kernel_launch(void* const* d_in, const int* in_sizes, int n_in,
                              void* d_out, int out_size)
{
    const int*   x     = (const int*)  d_in[0];
    const float* emb   = (const float*)d_in[1];
    const float* W_ih  = (const float*)d_in[2];
    const float* W_hh  = (const float*)d_in[3];
    const float* b_ih  = (const float*)d_in[4];
    const float* b_hh  = (const float*)d_in[5];
    const float* W_out = (const float*)d_in[6];
    const float* b_out = (const float*)d_in[7];
    float* out = (float*)d_out;

    gather_kernel<<<MM, 64>>>(x, emb);
    roundw_kernel<<<VV, 256>>>(W_out);
    inproj_kernel<<<dim3(MM / 256, 768 / 16), 256>>>(W_ih, b_ih);
    gru_kernel<<<32, 384>>>(W_hh, b_hh);
    gemm_out_kernel<<<dim3(VV / 128, MM / 128), 256>>>(b_out, x, out);
}